// round 3
// baseline (speedup 1.0000x reference)
#include <cuda_runtime.h>
#include <cuda_fp16.h>

// SemiConv2d (tropical conv): out[n,oc,h,w] = max_{ic,kh,kw} min(xpad, K)
// x: (8,32,96,96) f32, K: (32,32,3,3) f32, out f32, pad=1 with -inf.
// fp16 HMNMX2, w-paired accumulators, pre-splatted k taps in smem.

#define N_      8
#define IC_     32
#define OC_     32
#define H_      96
#define W_      96
#define TILE_H  4
#define XROWS   6            // TILE_H + 2 halo rows
#define XS_STRIDE 100        // halves per row (col0 & col97 = -inf halo; even stride)
#define OC_PER_BLK 16
#define THREADS 384

__global__ __launch_bounds__(THREADS)
void semiconv2d_h2w(const float* __restrict__ x,
                    const float* __restrict__ kern,
                    float* __restrict__ out) {
    extern __shared__ __align__(16) char smraw[];
    __half*  xs = (__half*)smraw;                                  // [IC][XROWS][XS_STRIDE]
    __half2* ks = (__half2*)(smraw + (size_t)IC_ * XROWS * XS_STRIDE * sizeof(__half)); // [16][IC][9] splatted

    const int tid    = threadIdx.x;
    const int n      = blockIdx.z;
    const int ocbase = blockIdx.y * OC_PER_BLK;
    const int h0     = blockIdx.x * TILE_H;
    const __half  NEGH = __ushort_as_half((unsigned short)0xFC00);  // -inf
    const __half2 NEG2 = __half2half2(NEGH);

    // ---- load x tile (f32 gmem -> f16 smem, -inf borders) ----
    const float* xn = x + (size_t)n * IC_ * H_ * W_;
    for (int e = tid; e < IC_ * XROWS * XS_STRIDE; e += THREADS) {
        int ic  = e / (XROWS * XS_STRIDE);
        int rem = e % (XROWS * XS_STRIDE);
        int r   = rem / XS_STRIDE;
        int c   = rem % XS_STRIDE;
        int g   = h0 - 1 + r;
        __half v = NEGH;
        if (c >= 1 && c <= W_ && g >= 0 && g < H_)
            v = __float2half_rn(xn[(ic * H_ + g) * W_ + (c - 1)]);
        xs[e] = v;
    }
    // ---- load kernel slice, each tap pre-splatted into both halves ----
    for (int e = tid; e < OC_PER_BLK * IC_ * 9; e += THREADS) {
        int ocl = e / (IC_ * 9);
        int rem = e % (IC_ * 9);
        __half kv = __float2half_rn(kern[(ocbase + ocl) * IC_ * 9 + rem]);
        ks[e] = __half2half2(kv);
    }
    __syncthreads();

    // thread -> (h within tile, 8-wide w strip, slot of 2 ocs)
    const int s    = tid % 48;
    const int slot = tid / 48;          // 0..7
    const int hl   = s / 12;            // 0..3
    const int w0   = (s % 12) * 8;      // even
    const int h    = h0 + hl;
    const int oca  = 2 * slot;          // local oc indices
    const int ocb  = 2 * slot + 1;

    // acc[oc][j] covers output cols (w0+2j, w0+2j+1)
    __half2 acc[2][4];
    #pragma unroll
    for (int p = 0; p < 2; p++)
        #pragma unroll
        for (int j = 0; j < 4; j++) acc[p][j] = NEG2;

    #pragma unroll 1
    for (int ic = 0; ic < IC_; ic++) {
        #pragma unroll
        for (int kh = 0; kh < 3; kh++) {
            const __half2* row = (const __half2*)(xs + (ic * XROWS + hl + kh) * XS_STRIDE + w0);
            __half2 V[5];
            #pragma unroll
            for (int i = 0; i < 5; i++) V[i] = row[i];
            __half2 S[4];
            #pragma unroll
            for (int j = 0; j < 4; j++)
                S[j] = __halves2half2(__high2half(V[j]), __low2half(V[j + 1]));

            const __half2* kpa = ks + (oca * IC_ + ic) * 9 + kh * 3;
            const __half2* kpb = ks + (ocb * IC_ + ic) * 9 + kh * 3;
            __half2 a0 = kpa[0], a1 = kpa[1], a2 = kpa[2];
            __half2 b0 = kpb[0], b1 = kpb[1], b2 = kpb[2];
            #pragma unroll
            for (int j = 0; j < 4; j++) {
                __half2 m = __hmin2(V[j], a0);
                m = __hmax2(m, __hmin2(S[j], a1));
                m = __hmax2(m, __hmin2(V[j + 1], a2));
                acc[0][j] = __hmax2(acc[0][j], m);
                __half2 q = __hmin2(V[j], b0);
                q = __hmax2(q, __hmin2(S[j], b1));
                q = __hmax2(q, __hmin2(V[j + 1], b2));
                acc[1][j] = __hmax2(acc[1][j], q);
            }
        }
    }

    // ---- write 2 oc x 8 w outputs as f32 ----
    #pragma unroll
    for (int p = 0; p < 2; p++) {
        int oc = ocbase + 2 * slot + p;
        float4* o = (float4*)(out + (((size_t)n * OC_ + oc) * H_ + h) * W_ + w0);
        float2 f0 = __half22float2(acc[p][0]);
        float2 f1 = __half22float2(acc[p][1]);
        float2 f2 = __half22float2(acc[p][2]);
        float2 f3 = __half22float2(acc[p][3]);
        o[0] = make_float4(f0.x, f0.y, f1.x, f1.y);
        o[1] = make_float4(f2.x, f2.y, f3.x, f3.y);
    }
}

extern "C" void kernel_launch(void* const* d_in, const int* in_sizes, int n_in,
                              void* d_out, int out_size) {
    const float* x = (const float*)d_in[0];
    const float* k = (const float*)d_in[1];
    float* out = (float*)d_out;

    size_t smem = (size_t)IC_ * XROWS * XS_STRIDE * sizeof(__half)
                + (size_t)OC_PER_BLK * IC_ * 9 * sizeof(__half2);  // 38400 + 18432 = 56832 B
    cudaFuncSetAttribute(semiconv2d_h2w,
                         cudaFuncAttributeMaxDynamicSharedMemorySize, (int)smem);
    dim3 grid(H_ / TILE_H, OC_ / OC_PER_BLK, N_);                  // 24 x 2 x 8 = 384
    semiconv2d_h2w<<<grid, THREADS, smem>>>(x, k, out);
}

// round 4
// speedup vs baseline: 1.0288x; 1.0288x over previous
#include <cuda_runtime.h>
#include <cuda_fp16.h>

// SemiConv2d (tropical conv): out[n,oc,h,w] = max_{ic,kh,kw} min(xpad, K)
// x: (8,32,96,96) f32, K: (32,32,3,3) f32, out f32, pad=1 with -inf.
// fp16 HMNMX2, oc-paired accumulators, same-register X splats (fold to
// half-lane operand modifiers -> near-pure HMNMX2 stream on the alu pipe).

#define N_      8
#define IC_     32
#define OC_     32
#define H_      96
#define W_      96
#define TILE_H  2
#define XROWS   4            // TILE_H + 2 halo rows
#define XS_STRIDE 102        // halves per row (col0 & col97 = -inf halo)
#define OC_PER_BLK 16
#define THREADS 192

__global__ __launch_bounds__(THREADS)
void semiconv2d_h2p(const float* __restrict__ x,
                    const float* __restrict__ kern,
                    float* __restrict__ out) {
    extern __shared__ __align__(16) char smraw[];
    __half*  xs = (__half*)smraw;                                  // [IC][XROWS][XS_STRIDE]
    __half2* ks = (__half2*)(smraw + (size_t)IC_ * XROWS * XS_STRIDE * sizeof(__half)); // [8 pairs][IC][9]

    const int tid    = threadIdx.x;
    const int n      = blockIdx.z;
    const int ocbase = blockIdx.y * OC_PER_BLK;
    const int h0     = blockIdx.x * TILE_H;
    const __half  NEGH = __ushort_as_half((unsigned short)0xFC00);  // -inf
    const __half2 NEG2 = __half2half2(NEGH);

    // ---- load x tile (f32 gmem -> f16 smem, -inf borders) ----
    const float* xn = x + (size_t)n * IC_ * H_ * W_;
    for (int e = tid; e < IC_ * XROWS * XS_STRIDE; e += THREADS) {
        int ic  = e / (XROWS * XS_STRIDE);
        int rem = e % (XROWS * XS_STRIDE);
        int r   = rem / XS_STRIDE;
        int c   = rem % XS_STRIDE;
        int g   = h0 - 1 + r;
        __half v = NEGH;
        if (c >= 1 && c <= W_ && g >= 0 && g < H_)
            v = __float2half_rn(xn[(ic * H_ + g) * W_ + (c - 1)]);
        xs[e] = v;
    }
    // ---- kernel slice, paired over adjacent ocs: ks[p][ic][t] = (k[2p], k[2p+1]) ----
    for (int e = tid; e < 8 * IC_ * 9; e += THREADS) {
        int p   = e / (IC_ * 9);
        int rem = e % (IC_ * 9);
        float a = kern[(ocbase + 2 * p)     * IC_ * 9 + rem];
        float b = kern[(ocbase + 2 * p + 1) * IC_ * 9 + rem];
        ks[e] = __floats2half2_rn(a, b);
    }
    __syncthreads();

    // thread -> (h row within tile, 8-wide w strip, one oc pair)
    const int s    = tid % 24;          // 24 spatial strips: 2 h x 12 w
    const int pair = tid / 24;          // 0..7
    const int hl   = s / 12;            // 0..1
    const int w0   = (s % 12) * 8;
    const int h    = h0 + hl;

    // acc[w] = (out[oc=2*pair][w], out[oc=2*pair+1][w])
    __half2 acc[8];
    #pragma unroll
    for (int w = 0; w < 8; w++) acc[w] = NEG2;

    const __half2* kbase = ks + (pair * IC_) * 9;

    #pragma unroll 1
    for (int ic = 0; ic < IC_; ic++) {
        #pragma unroll
        for (int kh = 0; kh < 3; kh++) {
            const __half2* row = (const __half2*)(xs + (ic * XROWS + hl + kh) * XS_STRIDE + w0);
            __half2 X[10];
            #pragma unroll
            for (int i = 0; i < 5; i++) {
                __half2 pv = row[i];
                X[2 * i]     = __low2half2(pv);    // same-register splat -> operand modifier
                X[2 * i + 1] = __high2half2(pv);
            }
            const __half2* kp = kbase + ic * 9 + kh * 3;
            __half2 k0 = kp[0], k1 = kp[1], k2 = kp[2];
            #pragma unroll
            for (int w = 0; w < 8; w++) {
                __half2 m = __hmin2(X[w], k0);
                m = __hmax2(m, __hmin2(X[w + 1], k1));
                m = __hmax2(m, __hmin2(X[w + 2], k2));
                acc[w] = __hmax2(acc[w], m);
            }
        }
    }

    // ---- write 2 oc x 8 w outputs as f32 ----
    int oc0 = ocbase + 2 * pair;
    float4* v0 = (float4*)(out + (((size_t)n * OC_ + oc0)     * H_ + h) * W_ + w0);
    float4* v1 = (float4*)(out + (((size_t)n * OC_ + oc0 + 1) * H_ + h) * W_ + w0);
    v0[0] = make_float4(__low2float(acc[0]), __low2float(acc[1]),
                        __low2float(acc[2]), __low2float(acc[3]));
    v0[1] = make_float4(__low2float(acc[4]), __low2float(acc[5]),
                        __low2float(acc[6]), __low2float(acc[7]));
    v1[0] = make_float4(__high2float(acc[0]), __high2float(acc[1]),
                        __high2float(acc[2]), __high2float(acc[3]));
    v1[1] = make_float4(__high2float(acc[4]), __high2float(acc[5]),
                        __high2float(acc[6]), __high2float(acc[7]));
}

extern "C" void kernel_launch(void* const* d_in, const int* in_sizes, int n_in,
                              void* d_out, int out_size) {
    const float* x = (const float*)d_in[0];
    const float* k = (const float*)d_in[1];
    float* out = (float*)d_out;

    size_t smem = (size_t)IC_ * XROWS * XS_STRIDE * sizeof(__half)
                + (size_t)8 * IC_ * 9 * sizeof(__half2);           // 26112 + 9216 = 35328 B
    cudaFuncSetAttribute(semiconv2d_h2p,
                         cudaFuncAttributeMaxDynamicSharedMemorySize, (int)smem);
    dim3 grid(H_ / TILE_H, OC_ / OC_PER_BLK, N_);                  // 48 x 2 x 8 = 768
    semiconv2d_h2p<<<grid, THREADS, smem>>>(x, k, out);
}